// round 8
// baseline (speedup 1.0000x reference)
#include <cuda_runtime.h>

#define Nn   128
#define Hh   2
#define Ll   1024
#define Cc   (Hh * Ll)      /* 2048 columns = h*L flattened */
#define PRED (Nn * Cc)      /* 262144 */

#define BLD  132            /* sB[n][k] lead dim: 16 x 128 (+4 pad) -> conflict-free frags */

__device__ float g_alpha[PRED];
__device__ float g_Ss[PRED];

// ---- tf32 helpers ----------------------------------------------------------
__device__ __forceinline__ unsigned f2tf32(float f) {
    unsigned u;
    asm("cvt.rna.tf32.f32 %0, %1;" : "=r"(u) : "f"(f));
    return u;
}
__device__ __forceinline__ void mma_tf32(float& d0, float& d1, float& d2, float& d3,
                                         unsigned a0, unsigned a1, unsigned a2, unsigned a3,
                                         unsigned b0, unsigned b1) {
    asm("mma.sync.aligned.m16n8k8.row.col.f32.tf32.tf32.f32 "
        "{%0,%1,%2,%3}, {%4,%5,%6,%7}, {%8,%9}, {%0,%1,%2,%3};"
        : "+f"(d0), "+f"(d1), "+f"(d2), "+f"(d3)
        : "r"(a0), "r"(a1), "r"(a2), "r"(a3), "r"(b0), "r"(b1));
}

// ---------------------------------------------------------------------------
// Kernel 1: per-(n,h)-row fused relu + cumsum + exponential-decay recurrence.
// Also emits the third output (Amat + I).
// ---------------------------------------------------------------------------
__global__ void __launch_bounds__(128) scan_kernel(const float* __restrict__ x,
                                                   const float* __restrict__ Amat,
                                                   const float* __restrict__ taus,
                                                   const float* __restrict__ r0dt,
                                                   float* __restrict__ out)
{
    int row  = blockIdx.x;          // n*H + h
    int t    = threadIdx.x;         // 0..127
    int lane = t & 31, wid = t >> 5;
    int base = row * Ll + t * 8;

    const float4* xv = reinterpret_cast<const float4*>(x + base);
    float4 v0 = xv[0], v1 = xv[1];
    float s[8] = { fmaxf(v0.x, 0.f), fmaxf(v0.y, 0.f), fmaxf(v0.z, 0.f), fmaxf(v0.w, 0.f),
                   fmaxf(v1.x, 0.f), fmaxf(v1.y, 0.f), fmaxf(v1.z, 0.f), fmaxf(v1.w, 0.f) };

    // third output: tempAmat.T = Amat + I  (first 128 blocks each do one row)
    if (row < 128) {
        int idx = row * 128 + t;
        out[2 * PRED + idx] = Amat[idx] + (row == t ? 1.f : 0.f);
    }

    float tau = taus[row];
    float R0  = r0dt[row];
    float d   = 1.f - 1.f / tau;

    float cum = 0.f, isv = 0.f;
#pragma unroll
    for (int k = 0; k < 8; k++) { cum += s[k]; isv = fmaf(d, isv, s[k]); }

    float d2 = d * d, d4 = d2 * d2, r8 = d4 * d4;   // d^8

    float inclI = isv, inclC = cum, rp = r8;
#pragma unroll
    for (int off = 1; off < 32; off <<= 1) {
        float ui = __shfl_up_sync(0xffffffffu, inclI, off);
        float uc = __shfl_up_sync(0xffffffffu, inclC, off);
        if (lane >= off) { inclI = fmaf(rp, ui, inclI); inclC += uc; }
        rp *= rp;
    }

    __shared__ float wI[4], wC[4];
    if (lane == 31) { wI[wid] = inclI; wC[wid] = inclC; }
    __syncthreads();

    float Rw = rp;                                  // d^256
    float exI = 0.f, exC = 0.f, aI = 0.f, aC = 0.f;
#pragma unroll
    for (int w = 0; w < 4; w++) {
        if (w == wid) { exI = aI; exC = aC; }
        aI = fmaf(Rw, aI, wI[w]);
        aC += wC[w];
    }

    float upI = __shfl_up_sync(0xffffffffu, inclI, 1);
    float upC = __shfl_up_sync(0xffffffffu, inclC, 1);
    if (lane == 0) { upI = 0.f; upC = 0.f; }
    float XI = fmaf(exI, __powf(r8, (float)lane), upI);
    float XC = upC + exC;

    float al[8], ss[8];
    float ci = XI, cc = XC;
#pragma unroll
    for (int k = 0; k < 8; k++) {
        ci = fmaf(d, ci, s[k]);
        cc += s[k];
        al[k] = 1.f - __expf(-R0 * ci);
        ss[k] = 1.f - cc;
    }

    float4* ga = reinterpret_cast<float4*>(g_alpha + base);
    ga[0] = make_float4(al[0], al[1], al[2], al[3]);
    ga[1] = make_float4(al[4], al[5], al[6], al[7]);
    float4* gs = reinterpret_cast<float4*>(g_Ss + base);
    gs[0] = make_float4(ss[0], ss[1], ss[2], ss[3]);
    gs[1] = make_float4(ss[4], ss[5], ss[6], ss[7]);
    float4* go = reinterpret_cast<float4*>(out + PRED + base);   // signal output
    go[0] = make_float4(s[0], s[1], s[2], s[3]);
    go[1] = make_float4(s[4], s[5], s[6], s[7]);
}

// ---------------------------------------------------------------------------
// Kernel 2 (tensor-core): Alpha = alpha + Amat @ alpha ; pred = Alpha * Ss.
// mma.sync.m16n8k8 tf32 with 3xTF32 split (Ahi.Bhi + Ahi.Blo + Alo.Bhi).
// Grid 128 blocks (one wave) x 16 cols; 256 threads = 8 warps x 16 rows.
// B (alpha tile) pre-split to tf32 hi/lo in smem, layout [n][k] ld=132
// (conflict-free fragment reads). A fragments loaded straight from L2.
// ---------------------------------------------------------------------------
__global__ void __launch_bounds__(256) gemm_kernel(const float* __restrict__ Amat,
                                                   float* __restrict__ out)
{
    __shared__ unsigned sBhi[16 * BLD];
    __shared__ unsigned sBlo[16 * BLD];

    int tid  = threadIdx.x;
    int lane = tid & 31, wy = tid >> 5;      // warp 0..7
    int c0 = blockIdx.x * 16;

    // ---- fill B tile: 128 m-rows x 16 cols of alpha -> tf32 hi/lo, [n][k] --
    // thread t: m = t>>1, cols (t&1)*8 .. +7  (two float4 loads)
    {
        int m  = tid >> 1;
        int j0 = (tid & 1) * 8;
        const float4* src = reinterpret_cast<const float4*>(&g_alpha[m * Cc + c0 + j0]);
        float4 q0 = src[0], q1 = src[1];
        float v[8] = { q0.x, q0.y, q0.z, q0.w, q1.x, q1.y, q1.z, q1.w };
#pragma unroll
        for (int j = 0; j < 8; j++) {
            unsigned hi = f2tf32(v[j]);
            float    lo = v[j] - __uint_as_float(hi);
            sBhi[(j0 + j) * BLD + m] = hi;
            sBlo[(j0 + j) * BLD + m] = f2tf32(lo);
        }
    }
    __syncthreads();

    int qr = lane >> 2;              // 0..7  (group id)
    int qc = lane & 3;               // 0..3  (thread in group)

    int ar = wy * 16 + qr;           // A fragment rows: ar, ar+8
    float dA[2][4] = { {0,0,0,0}, {0,0,0,0} };   // [ntile][reg]

#pragma unroll
    for (int kk = 0; kk < 16; kk++) {
        int k8 = kk * 8;
        // A fragment (row-major 16x8 at (wy*16, k8))
        float fa0 = Amat[ar * 128 + k8 + qc];
        float fa1 = Amat[(ar + 8) * 128 + k8 + qc];
        float fa2 = Amat[ar * 128 + k8 + qc + 4];
        float fa3 = Amat[(ar + 8) * 128 + k8 + qc + 4];
        unsigned a0h = f2tf32(fa0), a1h = f2tf32(fa1);
        unsigned a2h = f2tf32(fa2), a3h = f2tf32(fa3);
        unsigned a0l = f2tf32(fa0 - __uint_as_float(a0h));
        unsigned a1l = f2tf32(fa1 - __uint_as_float(a1h));
        unsigned a2l = f2tf32(fa2 - __uint_as_float(a2h));
        unsigned a3l = f2tf32(fa3 - __uint_as_float(a3h));

#pragma unroll
        for (int nt = 0; nt < 2; nt++) {
            int n = nt * 8 + qr;
            unsigned b0h = sBhi[n * BLD + k8 + qc];
            unsigned b1h = sBhi[n * BLD + k8 + qc + 4];
            unsigned b0l = sBlo[n * BLD + k8 + qc];
            unsigned b1l = sBlo[n * BLD + k8 + qc + 4];
            mma_tf32(dA[nt][0], dA[nt][1], dA[nt][2], dA[nt][3],
                     a0h, a1h, a2h, a3h, b0h, b1h);
            mma_tf32(dA[nt][0], dA[nt][1], dA[nt][2], dA[nt][3],
                     a0h, a1h, a2h, a3h, b0l, b1l);
            mma_tf32(dA[nt][0], dA[nt][1], dA[nt][2], dA[nt][3],
                     a0l, a1l, a2l, a3l, b0h, b1h);
        }
    }

    // ---- epilogue: (D + alpha) * Ss -> out -------------------------------
#pragma unroll
    for (int nt = 0; nt < 2; nt++) {
        int gc = c0 + nt * 8 + 2 * qc;
        int r0 = wy * 16 + qr;
        int r1 = r0 + 8;
        float2 al0 = *reinterpret_cast<const float2*>(&g_alpha[r0 * Cc + gc]);
        float2 ss0 = *reinterpret_cast<const float2*>(&g_Ss[r0 * Cc + gc]);
        float2 al1 = *reinterpret_cast<const float2*>(&g_alpha[r1 * Cc + gc]);
        float2 ss1 = *reinterpret_cast<const float2*>(&g_Ss[r1 * Cc + gc]);
        float2 o0 = make_float2((dA[nt][0] + al0.x) * ss0.x,
                                (dA[nt][1] + al0.y) * ss0.y);
        float2 o1 = make_float2((dA[nt][2] + al1.x) * ss1.x,
                                (dA[nt][3] + al1.y) * ss1.y);
        *reinterpret_cast<float2*>(&out[r0 * Cc + gc]) = o0;
        *reinterpret_cast<float2*>(&out[r1 * Cc + gc]) = o1;
    }
}

extern "C" void kernel_launch(void* const* d_in, const int* in_sizes, int n_in,
                              void* d_out, int out_size)
{
    const float* x    = (const float*)d_in[0];
    const float* Amat = (const float*)d_in[1];
    const float* taus = (const float*)d_in[2];
    const float* r0   = (const float*)d_in[3];
    float* out = (float*)d_out;

    (void)in_sizes; (void)n_in; (void)out_size;

    scan_kernel<<<Nn * Hh, 128>>>(x, Amat, taus, r0, out);
    gemm_kernel<<<128, 256>>>(Amat, out);
}

// round 9
// speedup vs baseline: 1.1239x; 1.1239x over previous
#include <cuda_runtime.h>

#define Nn   128
#define Hh   2
#define Ll   1024
#define Cc   (Hh * Ll)      /* 2048 columns = h*L flattened */
#define PRED (Nn * Cc)      /* 262144 */

#define ALD  132            /* sA[row][k] lead dim (conflict-free fragments) */
#define BLD  132            /* sB[n][k] lead dim */
#define SMEM_FLOATS (128 * ALD + 2 * 16 * BLD)   /* 16896 + 4224 = 21120 */
#define SMEM_BYTES  (SMEM_FLOATS * 4)            /* 84480 */

__device__ float g_alpha[PRED];
__device__ float g_Ss[PRED];

// ---- tf32 helpers ----------------------------------------------------------
__device__ __forceinline__ unsigned f2tf32(float f) {
    unsigned u;
    asm("cvt.rna.tf32.f32 %0, %1;" : "=r"(u) : "f"(f));
    return u;
}
__device__ __forceinline__ void mma_tf32(float& d0, float& d1, float& d2, float& d3,
                                         unsigned a0, unsigned a1, unsigned a2, unsigned a3,
                                         unsigned b0, unsigned b1) {
    asm("mma.sync.aligned.m16n8k8.row.col.f32.tf32.tf32.f32 "
        "{%0,%1,%2,%3}, {%4,%5,%6,%7}, {%8,%9}, {%0,%1,%2,%3};"
        : "+f"(d0), "+f"(d1), "+f"(d2), "+f"(d3)
        : "r"(a0), "r"(a1), "r"(a2), "r"(a3), "r"(b0), "r"(b1));
}
__device__ __forceinline__ void cp_async16(unsigned smem_addr, const void* gptr) {
    asm volatile("cp.async.cg.shared.global [%0], [%1], 16;"
                 :: "r"(smem_addr), "l"(gptr) : "memory");
}

// ---------------------------------------------------------------------------
// Kernel 1: per-(n,h)-row fused relu + cumsum + exponential-decay recurrence.
// Also emits the third output (Amat + I).
// ---------------------------------------------------------------------------
__global__ void __launch_bounds__(128) scan_kernel(const float* __restrict__ x,
                                                   const float* __restrict__ Amat,
                                                   const float* __restrict__ taus,
                                                   const float* __restrict__ r0dt,
                                                   float* __restrict__ out)
{
    int row  = blockIdx.x;          // n*H + h
    int t    = threadIdx.x;         // 0..127
    int lane = t & 31, wid = t >> 5;
    int base = row * Ll + t * 8;

    const float4* xv = reinterpret_cast<const float4*>(x + base);
    float4 v0 = xv[0], v1 = xv[1];
    float s[8] = { fmaxf(v0.x, 0.f), fmaxf(v0.y, 0.f), fmaxf(v0.z, 0.f), fmaxf(v0.w, 0.f),
                   fmaxf(v1.x, 0.f), fmaxf(v1.y, 0.f), fmaxf(v1.z, 0.f), fmaxf(v1.w, 0.f) };

    // third output: tempAmat.T = Amat + I  (first 128 blocks each do one row)
    if (row < 128) {
        int idx = row * 128 + t;
        out[2 * PRED + idx] = Amat[idx] + (row == t ? 1.f : 0.f);
    }

    float tau = taus[row];
    float R0  = r0dt[row];
    float d   = 1.f - 1.f / tau;

    float cum = 0.f, isv = 0.f;
#pragma unroll
    for (int k = 0; k < 8; k++) { cum += s[k]; isv = fmaf(d, isv, s[k]); }

    float d2 = d * d, d4 = d2 * d2, r8 = d4 * d4;   // d^8

    float inclI = isv, inclC = cum, rp = r8;
#pragma unroll
    for (int off = 1; off < 32; off <<= 1) {
        float ui = __shfl_up_sync(0xffffffffu, inclI, off);
        float uc = __shfl_up_sync(0xffffffffu, inclC, off);
        if (lane >= off) { inclI = fmaf(rp, ui, inclI); inclC += uc; }
        rp *= rp;
    }

    __shared__ float wI[4], wC[4];
    if (lane == 31) { wI[wid] = inclI; wC[wid] = inclC; }
    __syncthreads();

    float Rw = rp;                                  // d^256
    float exI = 0.f, exC = 0.f, aI = 0.f, aC = 0.f;
#pragma unroll
    for (int w = 0; w < 4; w++) {
        if (w == wid) { exI = aI; exC = aC; }
        aI = fmaf(Rw, aI, wI[w]);
        aC += wC[w];
    }

    float upI = __shfl_up_sync(0xffffffffu, inclI, 1);
    float upC = __shfl_up_sync(0xffffffffu, inclC, 1);
    if (lane == 0) { upI = 0.f; upC = 0.f; }
    float XI = fmaf(exI, __powf(r8, (float)lane), upI);
    float XC = upC + exC;

    float al[8], ss[8];
    float ci = XI, cc = XC;
#pragma unroll
    for (int k = 0; k < 8; k++) {
        ci = fmaf(d, ci, s[k]);
        cc += s[k];
        al[k] = 1.f - __expf(-R0 * ci);
        ss[k] = 1.f - cc;
    }

    float4* ga = reinterpret_cast<float4*>(g_alpha + base);
    ga[0] = make_float4(al[0], al[1], al[2], al[3]);
    ga[1] = make_float4(al[4], al[5], al[6], al[7]);
    float4* gs = reinterpret_cast<float4*>(g_Ss + base);
    gs[0] = make_float4(ss[0], ss[1], ss[2], ss[3]);
    gs[1] = make_float4(ss[4], ss[5], ss[6], ss[7]);
    float4* go = reinterpret_cast<float4*>(out + PRED + base);   // signal output
    go[0] = make_float4(s[0], s[1], s[2], s[3]);
    go[1] = make_float4(s[4], s[5], s[6], s[7]);
}

// ---------------------------------------------------------------------------
// Kernel 2 (tensor-core): Alpha = alpha + Amat @ alpha ; pred = Alpha * Ss.
// mma.sync.m16n8k8 tf32, 3xTF32 split. Grid 128 blocks (one wave) x 16 cols;
// 8 warps x 16 rows. Amat staged in smem via cp.async (mainloop = LDS only).
// ---------------------------------------------------------------------------
__global__ void __launch_bounds__(256, 1) gemm_kernel(const float* __restrict__ Amat,
                                                      float* __restrict__ out)
{
    extern __shared__ float smem[];
    float*    sA   = smem;                                    // [128][ALD] raw fp32
    unsigned* sBhi = reinterpret_cast<unsigned*>(smem + 128 * ALD);
    unsigned* sBlo = sBhi + 16 * BLD;

    int tid  = threadIdx.x;
    int lane = tid & 31, wy = tid >> 5;      // warp 0..7
    int c0 = blockIdx.x * 16;

    unsigned sAaddr = (unsigned)__cvta_generic_to_shared(sA);

    // ---- A tile: full Amat 128x128 via cp.async (4096 16B chunks / 256 thr) --
#pragma unroll
    for (int j = 0; j < 16; j++) {
        int i = j * 256 + tid;
        int r = i >> 5, cq = i & 31;         // row, 4-float chunk
        cp_async16(sAaddr + (unsigned)(r * ALD + cq * 4) * 4,
                   &Amat[r * 128 + cq * 4]);
    }
    asm volatile("cp.async.commit_group;" ::: "memory");

    // ---- B tile: 128 m-rows x 16 cols of alpha -> tf32 hi/lo, [n][k] -------
    {
        int m  = tid >> 1;
        int j0 = (tid & 1) * 8;
        const float4* src = reinterpret_cast<const float4*>(&g_alpha[m * Cc + c0 + j0]);
        float4 q0 = src[0], q1 = src[1];
        float v[8] = { q0.x, q0.y, q0.z, q0.w, q1.x, q1.y, q1.z, q1.w };
#pragma unroll
        for (int j = 0; j < 8; j++) {
            unsigned hi = f2tf32(v[j]);
            float    lo = v[j] - __uint_as_float(hi);
            sBhi[(j0 + j) * BLD + m] = hi;
            sBlo[(j0 + j) * BLD + m] = f2tf32(lo);
        }
    }
    asm volatile("cp.async.wait_group 0;" ::: "memory");
    __syncthreads();

    int qr = lane >> 2;              // 0..7
    int qc = lane & 3;               // 0..3

    int ar = wy * 16 + qr;           // A fragment rows: ar, ar+8
    const float* aR0 = &sA[ar * ALD];
    const float* aR1 = &sA[(ar + 8) * ALD];
    float dA[2][4] = { {0,0,0,0}, {0,0,0,0} };

#pragma unroll
    for (int kk = 0; kk < 16; kk++) {
        int k8 = kk * 8;
        float fa0 = aR0[k8 + qc];
        float fa1 = aR1[k8 + qc];
        float fa2 = aR0[k8 + qc + 4];
        float fa3 = aR1[k8 + qc + 4];
        unsigned a0h = f2tf32(fa0), a1h = f2tf32(fa1);
        unsigned a2h = f2tf32(fa2), a3h = f2tf32(fa3);
        unsigned a0l = f2tf32(fa0 - __uint_as_float(a0h));
        unsigned a1l = f2tf32(fa1 - __uint_as_float(a1h));
        unsigned a2l = f2tf32(fa2 - __uint_as_float(a2h));
        unsigned a3l = f2tf32(fa3 - __uint_as_float(a3h));

#pragma unroll
        for (int nt = 0; nt < 2; nt++) {
            int n = nt * 8 + qr;
            unsigned b0h = sBhi[n * BLD + k8 + qc];
            unsigned b1h = sBhi[n * BLD + k8 + qc + 4];
            unsigned b0l = sBlo[n * BLD + k8 + qc];
            unsigned b1l = sBlo[n * BLD + k8 + qc + 4];
            mma_tf32(dA[nt][0], dA[nt][1], dA[nt][2], dA[nt][3],
                     a0h, a1h, a2h, a3h, b0h, b1h);
            mma_tf32(dA[nt][0], dA[nt][1], dA[nt][2], dA[nt][3],
                     a0h, a1h, a2h, a3h, b0l, b1l);
            mma_tf32(dA[nt][0], dA[nt][1], dA[nt][2], dA[nt][3],
                     a0l, a1l, a2l, a3l, b0h, b1h);
        }
    }

    // ---- epilogue: (D + alpha) * Ss -> out -------------------------------
#pragma unroll
    for (int nt = 0; nt < 2; nt++) {
        int gc = c0 + nt * 8 + 2 * qc;
        int r0 = wy * 16 + qr;
        int r1 = r0 + 8;
        float2 al0 = *reinterpret_cast<const float2*>(&g_alpha[r0 * Cc + gc]);
        float2 ss0 = *reinterpret_cast<const float2*>(&g_Ss[r0 * Cc + gc]);
        float2 al1 = *reinterpret_cast<const float2*>(&g_alpha[r1 * Cc + gc]);
        float2 ss1 = *reinterpret_cast<const float2*>(&g_Ss[r1 * Cc + gc]);
        float2 o0 = make_float2((dA[nt][0] + al0.x) * ss0.x,
                                (dA[nt][1] + al0.y) * ss0.y);
        float2 o1 = make_float2((dA[nt][2] + al1.x) * ss1.x,
                                (dA[nt][3] + al1.y) * ss1.y);
        *reinterpret_cast<float2*>(&out[r0 * Cc + gc]) = o0;
        *reinterpret_cast<float2*>(&out[r1 * Cc + gc]) = o1;
    }
}

extern "C" void kernel_launch(void* const* d_in, const int* in_sizes, int n_in,
                              void* d_out, int out_size)
{
    const float* x    = (const float*)d_in[0];
    const float* Amat = (const float*)d_in[1];
    const float* taus = (const float*)d_in[2];
    const float* r0   = (const float*)d_in[3];
    float* out = (float*)d_out;

    (void)in_sizes; (void)n_in; (void)out_size;

    cudaFuncSetAttribute(gemm_kernel, cudaFuncAttributeMaxDynamicSharedMemorySize,
                         SMEM_BYTES);

    scan_kernel<<<Nn * Hh, 128>>>(x, Amat, taus, r0, out);
    gemm_kernel<<<128, 256, SMEM_BYTES>>>(Amat, out);
}